// round 3
// baseline (speedup 1.0000x reference)
#include <cuda_runtime.h>

// Depthwise 3x3 conv with hard-one-hot kernel == pure spatial shift, zero pad:
//   out[b,c,h,w] = x[b,c, h+dy, w+dx],  (dy,dx) = argmax(|weight|) - 1
//
// One warp per TWO image rows (row gw and row gw + nrows/2 -> same h, same
// plane geometry, so the row-bounds branch stays warp-uniform and is shared).
// Each lane loads 4 aligned float4 front-batched (MLP=4), resolves the +-1
// horizontal shift via register shuffle (the value shuffled past lane 0/31 is
// exactly the zero-padding), then stores 4 aligned float4.

#define NROWS_HALF 131072   // (16*64*256*256 / 256) / 2

__device__ __forceinline__ void shift_row(
    const float4 r0, const float4 r1, int dx, int lane,
    float4& o0, float4& o1)
{
    if (dx == 0) {
        o0 = r0; o1 = r1;
    } else if (dx > 0) {
        float nxt = __shfl_down_sync(0xffffffffu, r0.x, 1);
        if (lane == 31) nxt = 0.0f;            // col 256 -> zero pad
        o0 = make_float4(r0.y, r0.z, r0.w, r1.x);
        o1 = make_float4(r1.y, r1.z, r1.w, nxt);
    } else {
        float prv = __shfl_up_sync(0xffffffffu, r1.w, 1);
        if (lane == 0) prv = 0.0f;             // col -1 -> zero pad
        o0 = make_float4(prv, r0.x, r0.y, r0.z);
        o1 = make_float4(r0.w, r1.x, r1.y, r1.z);
    }
}

__global__ __launch_bounds__(256) void shift_row2_kernel(
    const float* __restrict__ x, const float* __restrict__ w9,
    float* __restrict__ out)
{
    __shared__ int2 s_shift;
    if (threadIdx.x == 0) {
        float best = -1.0f;
        int bi = 0;
        #pragma unroll
        for (int i = 0; i < 9; ++i) {
            float a = fabsf(w9[i]);
            if (a > best) { best = a; bi = i; }  // first occurrence wins (jnp.argmax)
        }
        s_shift = make_int2(bi / 3 - 1, bi % 3 - 1);
    }
    __syncthreads();
    const int dy = s_shift.x;
    const int dx = s_shift.y;

    const int gw   = (blockIdx.x * blockDim.x + threadIdx.x) >> 5;  // row id A
    const int lane = threadIdx.x & 31;

    const int h  = gw & 255;                  // same for both rows
    const int sh = h + dy;
    const size_t planeA = (size_t)(gw >> 8);
    const size_t planeB = planeA + (NROWS_HALF >> 8);

    float4 a0, a1, b0, b1;
    const bool inb = ((unsigned)sh < 256u);   // warp-uniform
    if (inb) {
        const float4* srcA = reinterpret_cast<const float4*>(
            x + ((planeA << 8) + (size_t)sh) * 256) + (lane << 1);
        const float4* srcB = reinterpret_cast<const float4*>(
            x + ((planeB << 8) + (size_t)sh) * 256) + (lane << 1);
        // front-batch all four 128-bit loads before any dependent op
        float4 ra0 = srcA[0];
        float4 ra1 = srcA[1];
        float4 rb0 = srcB[0];
        float4 rb1 = srcB[1];
        shift_row(ra0, ra1, dx, lane, a0, a1);
        shift_row(rb0, rb1, dx, lane, b0, b1);
    } else {
        a0 = make_float4(0.f, 0.f, 0.f, 0.f);
        a1 = a0; b0 = a0; b1 = a0;
    }

    float4* dstA = reinterpret_cast<float4*>(out) + ((size_t)gw << 6) + (lane << 1);
    float4* dstB = dstA + ((size_t)NROWS_HALF << 6);
    dstA[0] = a0;
    dstA[1] = a1;
    dstB[0] = b0;
    dstB[1] = b1;
}

extern "C" void kernel_launch(void* const* d_in, const int* in_sizes, int n_in,
                              void* d_out, int out_size) {
    const float* x = (const float*)d_in[0];
    const float* w = (const float*)d_in[1];
    float* out = (float*)d_out;

    // nrows = out_size/256 = 262144 ; each warp does 2 rows -> 131072 warps
    int warps  = (out_size >> 8) >> 1;
    int blocks = warps >> 3;               // 8 warps per 256-thread block
    shift_row2_kernel<<<blocks, 256>>>(x, w, out);
}